// round 16
// baseline (speedup 1.0000x reference)
#include <cuda_runtime.h>
#include <cuda_bf16.h>
#include <cstdint>

// ---------------------------------------------------------------------------
// T2FN on GB300:
//  Stage 1 (k_build_F): blocks 0..255: per-b persistent HMMA GEMM AV@X -> F
//                       blocks 256..295: W1 fp32 -> bf16 hi/lo plane convert
//  Stage 2 (k_gemm_mma): h1_pre = F @ W1planes; split-K 148 CTAs, 512 thr,
//                        pure cp.async double-buffered, zero in-loop converts
//  Stage 3 (k_finish):   reduce 148 partials + MLP tail
// ---------------------------------------------------------------------------

#define B_    128
#define T_    64
#define ADIM  48
#define XDIM  96
#define PF    128
#define NIJ   2401        // 49*49
#define KX    97          // X+1
#define KXP   98
#define FROWP 117664u     // padded pairs per b
#define NFLATK 235328u    // padded flat-k rows (3677*64)
#define NCHUNK 3677       // chunks of 32 pairs / 64 flat-k
#define NSPLIT 148
#define WSTR  68          // W1 plane row stride (words)

__device__ uint32_t g_Fhi[(size_t)B_ * FROWP];
__device__ uint32_t g_Flo[(size_t)B_ * FROWP];
__device__ uint32_t g_W1hi[(size_t)NFLATK * WSTR];   // zero-init; pad rows stay 0
__device__ uint32_t g_W1lo[(size_t)NFLATK * WSTR];
__device__ float    g_part[(size_t)NSPLIT * B_ * PF];

static __device__ __forceinline__ uint32_t cvthi(float v0, float v1) {
    uint32_t h;
    asm("cvt.rn.bf16x2.f32 %0, %1, %2;" : "=r"(h) : "f"(v1), "f"(v0));
    return h;
}
static __device__ __forceinline__ void cvt2(float v0, float v1, uint32_t& h, uint32_t& l) {
    uint32_t hh = cvthi(v0, v1);
    float h0 = __uint_as_float(hh << 16);
    float h1 = __uint_as_float(hh & 0xFFFF0000u);
    float r0 = v0 - h0, r1 = v1 - h1;
    asm("cvt.rn.bf16x2.f32 %0, %1, %2;" : "=r"(l) : "f"(r1), "f"(r0));
    h = hh;
}
static __device__ __forceinline__ uint32_t smem_u32(const void* p) {
    uint32_t a;
    asm("{ .reg .u64 t; cvta.to.shared.u64 t, %1; cvt.u32.u64 %0, t; }" : "=r"(a) : "l"(p));
    return a;
}
#define CPA16(dst, src) \
    asm volatile("cp.async.cg.shared.global [%0], [%1], 16;" :: "r"(dst), "l"(src))

static __device__ __forceinline__ void mma_bf16(float* d, const uint32_t* a,
                                                const uint32_t* b) {
    asm volatile(
        "mma.sync.aligned.m16n8k16.row.col.f32.bf16.bf16.f32 "
        "{%0,%1,%2,%3}, {%4,%5,%6,%7}, {%8,%9}, {%0,%1,%2,%3};"
        : "+f"(d[0]), "+f"(d[1]), "+f"(d[2]), "+f"(d[3])
        : "r"(a[0]), "r"(a[1]), "r"(a[2]), "r"(a[3]), "r"(b[0]), "r"(b[1]));
}
static __device__ __forceinline__ void ldsm4(uint32_t* r, uint32_t addr) {
    asm volatile("ldmatrix.sync.aligned.m8n8.x4.shared.b16 {%0,%1,%2,%3}, [%4];"
                 : "=r"(r[0]), "=r"(r[1]), "=r"(r[2]), "=r"(r[3]) : "r"(addr));
}
static __device__ __forceinline__ void ldsm4t(uint32_t* r, uint32_t addr) {
    asm volatile("ldmatrix.sync.aligned.m8n8.x4.trans.shared.b16 {%0,%1,%2,%3}, [%4];"
                 : "=r"(r[0]), "=r"(r[1]), "=r"(r[2]), "=r"(r[3]) : "r"(addr));
}

static constexpr int PSTR = 36;   // A-plane row stride (u32 words)
static constexpr int XSTR = 68;   // [k][n] bf16 plane row stride (u32 words)

// ===========================================================================
// Stage 1 smem (words)
static constexpr int S1_ALO = 4608;                  // Ahi @0 (128*36)
static constexpr int S1_XHI = 9216;                  // Xhi [64 t][68]
static constexpr int S1_XLO = S1_XHI + 64 * XSTR;    // 13568
static constexpr int S1_AUD = S1_XLO + 64 * XSTR;    // 17920
static constexpr int S1_VID = S1_AUD + T_ * 49;      // 21056
static constexpr int S1_WORDS = S1_VID + T_ * 49;    // 24192
static constexpr int S1_BYTES = S1_WORDS * 4;        // 96768

__global__ __launch_bounds__(256, 2)
void k_build_F(const float* __restrict__ audio,
               const float* __restrict__ video,
               const float* __restrict__ text,
               const float* __restrict__ W1) {
    const int tid = threadIdx.x;

    // ---------------- W1 converter blocks ----------------
    if (blockIdx.x >= 256) {
        const int cid2 = blockIdx.x - 256;            // 0..39
        uint32_t r0 = (uint32_t)cid2 * 5884u;
        uint32_t r1 = r0 + 5884u;
        if (r1 > NFLATK) r1 = NFLATK;
        const int sub = tid >> 5;                     // row in group of 8
        const int q   = tid & 31;                     // uint4 col (4 floats)
#pragma unroll 2
        for (uint32_t rr = r0 + sub; rr < r1; rr += 8) {
            uint32_t ij = rr / KXP;
            uint32_t cc = rr - ij * KXP;
            if (cc < KX && ij < NIJ) {
                const float4 w = *reinterpret_cast<const float4*>(
                    W1 + ((size_t)ij * KX + cc) * PF + q * 4);
                uint32_t h0, l0, h1, l1;
                cvt2(w.x, w.y, h0, l0);
                cvt2(w.z, w.w, h1, l1);
                size_t ro = (size_t)rr * WSTR + q * 2;
                *reinterpret_cast<uint2*>(&g_W1hi[ro]) = make_uint2(h0, h1);
                *reinterpret_cast<uint2*>(&g_W1lo[ro]) = make_uint2(l0, l1);
            }
        }
        return;
    }

    // ---------------- build-F blocks ----------------
    extern __shared__ uint32_t smw[];
    uint32_t* Ahi = smw;
    uint32_t* Alo = smw + S1_ALO;
    uint32_t* Xhi = smw + S1_XHI;
    uint32_t* Xlo = smw + S1_XLO;
    uint32_t* stg = smw;                 // epilogue overlay
    float* aud = reinterpret_cast<float*>(smw + S1_AUD);
    float* vid = reinterpret_cast<float*>(smw + S1_VID);

    const int b      = blockIdx.x >> 1;
    const int half   = blockIdx.x & 1;
    const int tstart = half ? 10 : 0;
    const int tend   = half ? 19 : 10;
    const int wid = tid >> 5;
    const int lid = tid & 31;
    const int g   = lid >> 2;
    const int tg  = lid & 3;
    const int mbase = (wid >> 2) * 64;
    const int nbase = (wid & 3) * 32;

#pragma unroll 3
    for (int idx = tid; idx < T_ * ADIM; idx += 256) {
        int t = idx / ADIM, c = idx - t * ADIM;
        aud[t * 49 + c] = audio[(size_t)b * (T_ * ADIM) + idx];
        vid[t * 49 + c] = video[(size_t)b * (T_ * ADIM) + idx];
    }
#pragma unroll
    for (int r = 0; r < 8; r++) {
        int t = wid * 8 + r;
        const float* trow = &text[((size_t)b * T_ + t) * XDIM];
#pragma unroll
        for (int h = 0; h < 2; h++) {
            int c  = lid + h * 32;
            int n0 = 2 * c, n1 = 2 * c + 1;
            float v0 = (n0 == 0) ? 1.f : ((n0 < KX) ? trow[n0 - 1] : 0.f);
            float v1 = (n1 < KX) ? trow[n1 - 1] : 0.f;
            uint32_t hw, lw;
            cvt2(v0, v1, hw, lw);
            Xhi[t * XSTR + c] = hw;
            Xlo[t * XSTR + c] = lw;
        }
    }
    __syncthreads();

    const uint32_t aOff = (uint32_t)(mbase + (lid & 15)) * (PSTR * 4) + (lid >> 4) * 16;
    const uint32_t aAhi = smem_u32(Ahi) + aOff;
    const uint32_t aAlo = smem_u32(Alo) + aOff;
    const uint32_t bOff = (uint32_t)(lid & 15) * (XSTR * 4) + (uint32_t)(nbase + (lid >> 4) * 8) * 2;
    const uint32_t aXhi = smem_u32(Xhi) + bOff;
    const uint32_t aXlo = smem_u32(Xlo) + bOff;

    for (int tile = tstart; tile < tend; tile++) {
        const int ij0 = tile * 128;

        // ---- AV planes [ijl][t-pair] ----
        {
            const int tp = tid & 31;
            const int r0 = tid >> 5;
            const int t0 = 2 * tp;
#pragma unroll 4
            for (int it = 0; it < 16; it++) {
                int ijl = it * 8 + r0;
                int ij  = ij0 + ijl;
                float v0 = 0.f, v1 = 0.f;
                if (ij < NIJ) {
                    int i = ij / 49;
                    int j = ij - i * 49;
                    float a0 = i ? aud[t0 * 49 + (i - 1)] : 1.f;
                    float a1 = i ? aud[(t0 + 1) * 49 + (i - 1)] : 1.f;
                    float w0 = j ? vid[t0 * 49 + (j - 1)] : 1.f;
                    float w1 = j ? vid[(t0 + 1) * 49 + (j - 1)] : 1.f;
                    v0 = a0 * w0;
                    v1 = a1 * w1;
                }
                uint32_t h, l;
                cvt2(v0, v1, h, l);
                Ahi[ijl * PSTR + tp] = h;
                Alo[ijl * PSTR + tp] = l;
            }
        }
        __syncthreads();

        // ---- 3-combo HMMA, K=64 ----
        float acc[4][4][4];
#pragma unroll
        for (int mt = 0; mt < 4; mt++)
#pragma unroll
            for (int nt = 0; nt < 4; nt++)
#pragma unroll
                for (int r = 0; r < 4; r++) acc[mt][nt][r] = 0.f;

#pragma unroll
        for (int ks = 0; ks < 4; ks++) {
            uint32_t bh[8], bl[8];
            const uint32_t bk = (uint32_t)ks * 16 * (XSTR * 4);
            ldsm4t(bh + 0, aXhi + bk);
            ldsm4t(bh + 4, aXhi + bk + 32);
            ldsm4t(bl + 0, aXlo + bk);
            ldsm4t(bl + 4, aXlo + bk + 32);
#pragma unroll
            for (int mt = 0; mt < 4; mt++) {
                const uint32_t am = (uint32_t)mt * 16 * (PSTR * 4) + (uint32_t)ks * 32;
                uint32_t ah[4], al[4];
                ldsm4(ah, aAhi + am);
                ldsm4(al, aAlo + am);
#pragma unroll
                for (int nt = 0; nt < 4; nt++) {
                    mma_bf16(acc[mt][nt], ah, &bh[2 * nt]);
                    mma_bf16(acc[mt][nt], ah, &bl[2 * nt]);
                    mma_bf16(acc[mt][nt], al, &bh[2 * nt]);
                }
            }
        }
        __syncthreads();

        const int nrows = (NIJ - ij0 < 128) ? (NIJ - ij0) : 128;
        const int nw = nrows * 49;
        const int nq = nw >> 2;
        const size_t gbase = (size_t)b * FROWP + (size_t)ij0 * 49;

        // ---- pass 1: hi plane (single cvt2; lo stashed into acc) ----
#pragma unroll
        for (int mt = 0; mt < 4; mt++) {
            int row = mbase + mt * 16 + g;
#pragma unroll
            for (int nt = 0; nt < 4; nt++) {
                int col = nbase + nt * 8 + 2 * tg;
                uint32_t h0, l0, h1, l1;
                cvt2(acc[mt][nt][0], acc[mt][nt][1], h0, l0);
                cvt2(acc[mt][nt][2], acc[mt][nt][3], h1, l1);
                acc[mt][nt][0] = __uint_as_float(l0);
                acc[mt][nt][1] = __uint_as_float(l1);
                if (col > 96) continue;
                int pr = col >> 1;
                stg[row * 49 + pr]       = h0;
                stg[(row + 8) * 49 + pr] = h1;
            }
        }
        __syncthreads();
        {
            const uint4* s4 = reinterpret_cast<const uint4*>(stg);
            uint4* d4 = reinterpret_cast<uint4*>(g_Fhi + gbase);
            for (int idx = tid; idx < nq; idx += 256) d4[idx] = s4[idx];
            for (int idx = (nq << 2) + tid; idx < nw; idx += 256)
                g_Fhi[gbase + idx] = stg[idx];
        }
        __syncthreads();

        // ---- pass 2: lo plane ----
#pragma unroll
        for (int mt = 0; mt < 4; mt++) {
            int row = mbase + mt * 16 + g;
#pragma unroll
            for (int nt = 0; nt < 4; nt++) {
                int col = nbase + nt * 8 + 2 * tg;
                if (col > 96) continue;
                int pr = col >> 1;
                stg[row * 49 + pr]       = __float_as_uint(acc[mt][nt][0]);
                stg[(row + 8) * 49 + pr] = __float_as_uint(acc[mt][nt][1]);
            }
        }
        __syncthreads();
        {
            const uint4* s4 = reinterpret_cast<const uint4*>(stg);
            uint4* d4 = reinterpret_cast<uint4*>(g_Flo + gbase);
            for (int idx = tid; idx < nq; idx += 256) d4[idx] = s4[idx];
            for (int idx = (nq << 2) + tid; idx < nw; idx += 256)
                g_Flo[gbase + idx] = stg[idx];
        }
        __syncthreads();
    }
}

// ===========================================================================
// Stage 2: split-K HMMA GEMM, pure-copy, double-buffered. grid 148, block 512.
// chunk = 32 pairs = 64 flat-k. Per buffer (words):
//   Ahi @0 (128*36=4608), Alo @4608, Bhi @9216 (64*68=4352), Blo @13568
static constexpr int BUFW    = 17920;            // words per buffer
static constexpr int S2_WORDS = 2 * BUFW;        // 35840
static constexpr int S2_BYTES = S2_WORDS * 4;    // 143360

__global__ __launch_bounds__(512, 1)
void k_gemm_mma() {
    extern __shared__ uint32_t smw[];
    const uint32_t smb = smem_u32(smw);

    const int tid = threadIdx.x;
    const int wid = tid >> 5;               // 0..15
    const int lid = tid & 31;
    const int mbase = (wid >> 2) * 32;      // 4 m-groups of 32 rows
    const int nbase = (wid & 3) * 32;       // 4 n-groups of 32 cols
    const int g  = lid >> 2;
    const int tg = lid & 3;

    const uint32_t aOff = (uint32_t)(mbase + (lid & 15)) * (PSTR * 4) + (lid >> 4) * 16;
    const uint32_t bOff = (uint32_t)(lid & 15) * (XSTR * 4) + (uint32_t)(nbase + (lid >> 4) * 8) * 2;

    float acc[2][4][4];
#pragma unroll
    for (int mt = 0; mt < 2; mt++)
#pragma unroll
        for (int nt = 0; nt < 4; nt++)
#pragma unroll
            for (int r = 0; r < 4; r++) acc[mt][nt][r] = 0.f;

    auto stage = [&](int c, int p) {
        const uint32_t kp_base = (uint32_t)c * 32u;     // pair offset
        const uint32_t fk_base = (uint32_t)c * 64u;     // flat-k row offset
        const uint32_t base = (uint32_t)(p * BUFW);
        // A: 2 planes x 128 rows x 8 uint4 = 2048 slots -> 4 iters of 512
#pragma unroll
        for (int it = 0; it < 2; it++) {
            int idx = it * 512 + tid;
            int row = idx >> 3;
            int q4  = (idx & 7) * 4;
            CPA16(smb + (base + row * PSTR + q4) * 4,
                  &g_Fhi[(size_t)row * FROWP + kp_base + q4]);
        }
#pragma unroll
        for (int it = 0; it < 2; it++) {
            int idx = it * 512 + tid;
            int row = idx >> 3;
            int q4  = (idx & 7) * 4;
            CPA16(smb + (base + 4608 + row * PSTR + q4) * 4,
                  &g_Flo[(size_t)row * FROWP + kp_base + q4]);
        }
        // B: 2 planes x 64 rows x 17 uint4 = 1088 slots each
#pragma unroll
        for (int it = 0; it < 3; it++) {
            int idx = it * 512 + tid;
            if (idx < 1088) {
                int r = idx / 17;
                int q = idx - r * 17;
                CPA16(smb + (base + 9216 + r * XSTR + q * 4) * 4,
                      &g_W1hi[(size_t)(fk_base + r) * WSTR + q * 4]);
            }
        }
#pragma unroll
        for (int it = 0; it < 3; it++) {
            int idx = it * 512 + tid;
            if (idx < 1088) {
                int r = idx / 17;
                int q = idx - r * 17;
                CPA16(smb + (base + 13568 + r * XSTR + q * 4) * 4,
                      &g_W1lo[(size_t)(fk_base + r) * WSTR + q * 4]);
            }
        }
        asm volatile("cp.async.commit_group;");
    };

    int c = blockIdx.x;
    stage(c, 0);
    int p = 0;

    for (; c < NCHUNK; c += NSPLIT, p ^= 1) {
        const int cn = c + NSPLIT;
        const bool hn = cn < NCHUNK;
        if (hn) {
            stage(cn, p ^ 1);
            asm volatile("cp.async.wait_group 1;");
        } else {
            asm volatile("cp.async.wait_group 0;");
        }
        __syncthreads();

        const uint32_t base = (uint32_t)(p * BUFW);
        const uint32_t aAhi = smb + base * 4 + aOff;
        const uint32_t aAlo = aAhi + 4608 * 4;
        const uint32_t aBhi = smb + (base + 9216) * 4 + bOff;
        const uint32_t aBlo = aBhi + 4352 * 4;

#pragma unroll
        for (int ks = 0; ks < 4; ks++) {
            uint32_t bh[8], bl[8];
            const uint32_t bk = (uint32_t)ks * 16 * (XSTR * 4);
            ldsm4t(bh + 0, aBhi + bk);
            ldsm4t(bh + 4, aBhi + bk + 32);
            ldsm4t(bl + 0, aBlo + bk);
            ldsm4t(bl + 4, aBlo + bk + 32);
#pragma unroll
            for (int mt = 0; mt < 2; mt++) {
                const uint32_t am = (uint32_t)mt * 16 * (PSTR * 4) + (uint32_t)ks * 32;
                uint32_t ah[4], al[4];
                ldsm4(ah, aAhi + am);
                ldsm4(al, aAlo + am);
#pragma unroll
                for (int nt = 0; nt < 4; nt++) {
                    mma_bf16(acc[mt][nt], ah, &bh[2 * nt]);
                    mma_bf16(acc[mt][nt], ah, &bl[2 * nt]);
                    mma_bf16(acc[mt][nt], al, &bh[2 * nt]);
                }
            }
        }
        __syncthreads();   // all reads of buffer p done before it is restaged
    }

    float* part = &g_part[(size_t)blockIdx.x * (B_ * PF)];
#pragma unroll
    for (int mt = 0; mt < 2; mt++) {
        int row = mbase + mt * 16 + g;
#pragma unroll
        for (int nt = 0; nt < 4; nt++) {
            int col = nbase + nt * 8 + 2 * tg;
            *reinterpret_cast<float2*>(&part[(size_t)row * PF + col]) =
                make_float2(acc[mt][nt][0], acc[mt][nt][1]);
            *reinterpret_cast<float2*>(&part[(size_t)(row + 8) * PF + col]) =
                make_float2(acc[mt][nt][2], acc[mt][nt][3]);
        }
    }
}

// ===========================================================================
__global__ void k_finish(const float* __restrict__ b1, const float* __restrict__ W2,
                         const float* __restrict__ b2, const float* __restrict__ W3,
                         const float* __restrict__ b3, float* __restrict__ out) {
    __shared__ float h1s[PF];
    __shared__ float red[PF];
    const int b = blockIdx.x;
    const int q = threadIdx.x;

    float s0 = 0.f, s1 = 0.f, s2 = 0.f, s3 = 0.f;
    const size_t off = (size_t)b * PF + q;
#pragma unroll 4
    for (int c = 0; c < NSPLIT; c += 4) {
        s0 += g_part[(size_t)(c + 0) * (B_ * PF) + off];
        s1 += g_part[(size_t)(c + 1) * (B_ * PF) + off];
        s2 += g_part[(size_t)(c + 2) * (B_ * PF) + off];
        s3 += g_part[(size_t)(c + 3) * (B_ * PF) + off];
    }
    float h1 = (s0 + s1) + (s2 + s3) + b1[q];
    h1s[q] = fmaxf(h1, 0.f);
    __syncthreads();

    float a0 = b2[q], a1 = 0.f, a2 = 0.f, a3 = 0.f;
#pragma unroll 8
    for (int pq = 0; pq < PF; pq += 4) {
        a0 = fmaf(h1s[pq + 0], W2[(pq + 0) * PF + q], a0);
        a1 = fmaf(h1s[pq + 1], W2[(pq + 1) * PF + q], a1);
        a2 = fmaf(h1s[pq + 2], W2[(pq + 2) * PF + q], a2);
        a3 = fmaf(h1s[pq + 3], W2[(pq + 3) * PF + q], a3);
    }
    float h2 = fmaxf((a0 + a1) + (a2 + a3), 0.f);

    red[q] = h2 * W3[q];
    __syncthreads();
    for (int s = 64; s > 0; s >>= 1) {
        if (q < s) red[q] += red[q + s];
        __syncthreads();
    }
    if (q == 0) {
        float z = red[0] + b3[0];
        out[b] = 6.f / (1.f + expf(-z)) - 3.f;
    }
}

// ---------------------------------------------------------------------------
extern "C" void kernel_launch(void* const* d_in, const int* in_sizes, int n_in,
                              void* d_out, int out_size) {
    const float* audio = (const float*)d_in[0];
    const float* video = (const float*)d_in[1];
    const float* text  = (const float*)d_in[2];
    const float* W1    = (const float*)d_in[3];
    const float* b1    = (const float*)d_in[4];
    const float* W2    = (const float*)d_in[5];
    const float* b2    = (const float*)d_in[6];
    const float* W3    = (const float*)d_in[7];
    const float* b3    = (const float*)d_in[8];
    float* out = (float*)d_out;

    cudaFuncSetAttribute(k_build_F, cudaFuncAttributeMaxDynamicSharedMemorySize, S1_BYTES);
    cudaFuncSetAttribute(k_gemm_mma, cudaFuncAttributeMaxDynamicSharedMemorySize, S2_BYTES);

    k_build_F<<<296, 256, S1_BYTES>>>(audio, video, text, W1);
    k_gemm_mma<<<NSPLIT, 512, S2_BYTES>>>();
    k_finish<<<128, 128>>>(b1, W2, b2, W3, b3, out);
}

// round 17
// speedup vs baseline: 2.9524x; 2.9524x over previous
#include <cuda_runtime.h>
#include <cuda_bf16.h>
#include <cstdint>

// ---------------------------------------------------------------------------
// T2FN on GB300 — hi/lo bf16 planes + ldmatrix fragments:
//  Stage 1 (k_build_F): persistent 296 CTAs, balanced (b,tile) work split,
//                       HMMA GEMM AV@X -> F planes, coalesced epilogue
//  Stage 2 (k_gemm_mma): h1_pre = F @ W1, split-K 296, cp.async A prefetch,
//                        k-major B + trans LDSM (R12-proven)
//  Stage 3 (k_finish):   reduce partials + MLP tail
// ---------------------------------------------------------------------------

#define B_    128
#define T_    64
#define ADIM  48
#define XDIM  96
#define PF    128
#define NIJ   2401        // 49*49
#define KX    97          // X+1
#define KXP   98
#define KPC   32          // pairs per chunk (64 flat k)
#define NCHUNK2 3677
#define FROWP 117664u     // padded pairs per b (3677*32)
#define NSPLIT 296
#define NUNITS 2432       // 128 b x 19 tiles

__device__ uint32_t g_Fhi[(size_t)B_ * FROWP];
__device__ uint32_t g_Flo[(size_t)B_ * FROWP];
__device__ float    g_part[(size_t)NSPLIT * B_ * PF];

static __device__ __forceinline__ uint32_t cvthi(float v0, float v1) {
    uint32_t h;
    asm("cvt.rn.bf16x2.f32 %0, %1, %2;" : "=r"(h) : "f"(v1), "f"(v0));
    return h;
}
static __device__ __forceinline__ void cvt2(float v0, float v1, uint32_t& h, uint32_t& l) {
    uint32_t hh = cvthi(v0, v1);
    float h0 = __uint_as_float(hh << 16);
    float h1 = __uint_as_float(hh & 0xFFFF0000u);
    float r0 = v0 - h0, r1 = v1 - h1;
    asm("cvt.rn.bf16x2.f32 %0, %1, %2;" : "=r"(l) : "f"(r1), "f"(r0));
    h = hh;
}
static __device__ __forceinline__ uint32_t smem_u32(const void* p) {
    uint32_t a;
    asm("{ .reg .u64 t; cvta.to.shared.u64 t, %1; cvt.u32.u64 %0, t; }" : "=r"(a) : "l"(p));
    return a;
}
#define CPA16(dst, src) \
    asm volatile("cp.async.cg.shared.global [%0], [%1], 16;" :: "r"(dst), "l"(src))

static __device__ __forceinline__ void mma_bf16(float* d, const uint32_t* a,
                                                const uint32_t* b) {
    asm volatile(
        "mma.sync.aligned.m16n8k16.row.col.f32.bf16.bf16.f32 "
        "{%0,%1,%2,%3}, {%4,%5,%6,%7}, {%8,%9}, {%0,%1,%2,%3};"
        : "+f"(d[0]), "+f"(d[1]), "+f"(d[2]), "+f"(d[3])
        : "r"(a[0]), "r"(a[1]), "r"(a[2]), "r"(a[3]), "r"(b[0]), "r"(b[1]));
}
static __device__ __forceinline__ void ldsm4(uint32_t* r, uint32_t addr) {
    asm volatile("ldmatrix.sync.aligned.m8n8.x4.shared.b16 {%0,%1,%2,%3}, [%4];"
                 : "=r"(r[0]), "=r"(r[1]), "=r"(r[2]), "=r"(r[3]) : "r"(addr));
}
static __device__ __forceinline__ void ldsm4t(uint32_t* r, uint32_t addr) {
    asm volatile("ldmatrix.sync.aligned.m8n8.x4.trans.shared.b16 {%0,%1,%2,%3}, [%4];"
                 : "=r"(r[0]), "=r"(r[1]), "=r"(r[2]), "=r"(r[3]) : "r"(addr));
}

static constexpr int PSTR = 36;   // A-plane row stride (u32 words)
static constexpr int XSTR = 68;   // [k][n] bf16 plane row stride (u32 words)

// ===========================================================================
// Stage 1 smem (words)
static constexpr int S1_ALO = 4608;                  // Ahi @0 (128*36)
static constexpr int S1_XHI = 9216;                  // Xhi [64 t][68]
static constexpr int S1_XLO = S1_XHI + 64 * XSTR;    // 13568
static constexpr int S1_AUD = S1_XLO + 64 * XSTR;    // 17920
static constexpr int S1_VID = S1_AUD + T_ * 49;      // 21056
static constexpr int S1_WORDS = S1_VID + T_ * 49;    // 24192
static constexpr int S1_BYTES = S1_WORDS * 4;        // 96768

__global__ __launch_bounds__(256, 2)
void k_build_F(const float* __restrict__ audio,
               const float* __restrict__ video,
               const float* __restrict__ text) {
    extern __shared__ uint32_t smw[];
    uint32_t* Ahi = smw;
    uint32_t* Alo = smw + S1_ALO;
    uint32_t* Xhi = smw + S1_XHI;
    uint32_t* Xlo = smw + S1_XLO;
    uint32_t* stg = smw;                 // epilogue overlay
    float* aud = reinterpret_cast<float*>(smw + S1_AUD);
    float* vid = reinterpret_cast<float*>(smw + S1_VID);

    const int tid = threadIdx.x;
    const int wid = tid >> 5;
    const int lid = tid & 31;
    const int g   = lid >> 2;
    const int tg  = lid & 3;
    const int mbase = (wid >> 2) * 64;
    const int nbase = (wid & 3) * 32;

    // balanced persistent work split: units u0..u1-1, unit = b*19 + tile
    const int u0 = (blockIdx.x * NUNITS) / NSPLIT;
    const int u1 = ((blockIdx.x + 1) * NUNITS) / NSPLIT;

    const uint32_t aOff = (uint32_t)(mbase + (lid & 15)) * (PSTR * 4) + (lid >> 4) * 16;
    const uint32_t aAhi = smem_u32(Ahi) + aOff;
    const uint32_t aAlo = smem_u32(Alo) + aOff;
    const uint32_t bOff = (uint32_t)(lid & 15) * (XSTR * 4) + (uint32_t)(nbase + (lid >> 4) * 8) * 2;
    const uint32_t aXhi = smem_u32(Xhi) + bOff;
    const uint32_t aXlo = smem_u32(Xlo) + bOff;

    int cur_b = -1;
    for (int u = u0; u < u1; u++) {
        const int b    = u / 19;
        const int tile = u - b * 19;
        const int ij0  = tile * 128;

        if (b != cur_b) {
            cur_b = b;
            __syncthreads();   // prior tile fully done before restaging X/aud/vid
#pragma unroll 3
            for (int idx = tid; idx < T_ * ADIM; idx += 256) {
                int t = idx / ADIM, c = idx - t * ADIM;
                aud[t * 49 + c] = audio[(size_t)b * (T_ * ADIM) + idx];
                vid[t * 49 + c] = video[(size_t)b * (T_ * ADIM) + idx];
            }
#pragma unroll
            for (int r = 0; r < 8; r++) {
                int t = wid * 8 + r;
                const float* trow = &text[((size_t)b * T_ + t) * XDIM];
#pragma unroll
                for (int h = 0; h < 2; h++) {
                    int c  = lid + h * 32;
                    int n0 = 2 * c, n1 = 2 * c + 1;
                    float v0 = (n0 == 0) ? 1.f : ((n0 < KX) ? trow[n0 - 1] : 0.f);
                    float v1 = (n1 < KX) ? trow[n1 - 1] : 0.f;
                    uint32_t hw, lw;
                    cvt2(v0, v1, hw, lw);
                    Xhi[t * XSTR + c] = hw;
                    Xlo[t * XSTR + c] = lw;
                }
            }
            __syncthreads();
        }

        // ---- AV planes [ijl][t-pair] ----
        {
            const int tp = tid & 31;
            const int r0 = tid >> 5;
            const int t0 = 2 * tp;
#pragma unroll 4
            for (int it = 0; it < 16; it++) {
                int ijl = it * 8 + r0;
                int ij  = ij0 + ijl;
                float v0 = 0.f, v1 = 0.f;
                if (ij < NIJ) {
                    int i = ij / 49;
                    int j = ij - i * 49;
                    float a0 = i ? aud[t0 * 49 + (i - 1)] : 1.f;
                    float a1 = i ? aud[(t0 + 1) * 49 + (i - 1)] : 1.f;
                    float w0 = j ? vid[t0 * 49 + (j - 1)] : 1.f;
                    float w1 = j ? vid[(t0 + 1) * 49 + (j - 1)] : 1.f;
                    v0 = a0 * w0;
                    v1 = a1 * w1;
                }
                uint32_t h, l;
                cvt2(v0, v1, h, l);
                Ahi[ijl * PSTR + tp] = h;
                Alo[ijl * PSTR + tp] = l;
            }
        }
        __syncthreads();

        // ---- 3-combo HMMA, K=64 ----
        float acc[4][4][4];
#pragma unroll
        for (int mt = 0; mt < 4; mt++)
#pragma unroll
            for (int nt = 0; nt < 4; nt++)
#pragma unroll
                for (int r = 0; r < 4; r++) acc[mt][nt][r] = 0.f;

#pragma unroll
        for (int ks = 0; ks < 4; ks++) {
            uint32_t bh[8], bl[8];
            const uint32_t bk = (uint32_t)ks * 16 * (XSTR * 4);
            ldsm4t(bh + 0, aXhi + bk);
            ldsm4t(bh + 4, aXhi + bk + 32);
            ldsm4t(bl + 0, aXlo + bk);
            ldsm4t(bl + 4, aXlo + bk + 32);
#pragma unroll
            for (int mt = 0; mt < 4; mt++) {
                const uint32_t am = (uint32_t)mt * 16 * (PSTR * 4) + (uint32_t)ks * 32;
                uint32_t ah[4], al[4];
                ldsm4(ah, aAhi + am);
                ldsm4(al, aAlo + am);
#pragma unroll
                for (int nt = 0; nt < 4; nt++) {
                    mma_bf16(acc[mt][nt], ah, &bh[2 * nt]);
                    mma_bf16(acc[mt][nt], ah, &bl[2 * nt]);
                    mma_bf16(acc[mt][nt], al, &bh[2 * nt]);
                }
            }
        }
        __syncthreads();   // fragment loads done before staging overwrite

        const int nrows = (NIJ - ij0 < 128) ? (NIJ - ij0) : 128;
        const int nw = nrows * 49;
        const int nq = nw >> 2;
        const size_t gbase = (size_t)b * FROWP + (size_t)ij0 * 49;

        // ---- pass 1: hi plane (single cvt2; lo stashed into acc) ----
#pragma unroll
        for (int mt = 0; mt < 4; mt++) {
            int row = mbase + mt * 16 + g;
#pragma unroll
            for (int nt = 0; nt < 4; nt++) {
                int col = nbase + nt * 8 + 2 * tg;
                uint32_t h0, l0, h1, l1;
                cvt2(acc[mt][nt][0], acc[mt][nt][1], h0, l0);
                cvt2(acc[mt][nt][2], acc[mt][nt][3], h1, l1);
                acc[mt][nt][0] = __uint_as_float(l0);
                acc[mt][nt][1] = __uint_as_float(l1);
                if (col > 96) continue;
                int pr = col >> 1;
                stg[row * 49 + pr]       = h0;
                stg[(row + 8) * 49 + pr] = h1;
            }
        }
        __syncthreads();
        {
            const uint4* s4 = reinterpret_cast<const uint4*>(stg);
            uint4* d4 = reinterpret_cast<uint4*>(g_Fhi + gbase);
            for (int idx = tid; idx < nq; idx += 256) d4[idx] = s4[idx];
            for (int idx = (nq << 2) + tid; idx < nw; idx += 256)
                g_Fhi[gbase + idx] = stg[idx];
        }
        __syncthreads();

        // ---- pass 2: lo plane ----
#pragma unroll
        for (int mt = 0; mt < 4; mt++) {
            int row = mbase + mt * 16 + g;
#pragma unroll
            for (int nt = 0; nt < 4; nt++) {
                int col = nbase + nt * 8 + 2 * tg;
                if (col > 96) continue;
                int pr = col >> 1;
                stg[row * 49 + pr]       = __float_as_uint(acc[mt][nt][0]);
                stg[(row + 8) * 49 + pr] = __float_as_uint(acc[mt][nt][1]);
            }
        }
        __syncthreads();
        {
            const uint4* s4 = reinterpret_cast<const uint4*>(stg);
            uint4* d4 = reinterpret_cast<uint4*>(g_Flo + gbase);
            for (int idx = tid; idx < nq; idx += 256) d4[idx] = s4[idx];
            for (int idx = (nq << 2) + tid; idx < nw; idx += 256)
                g_Flo[gbase + idx] = stg[idx];
        }
        __syncthreads();
    }
}

// ===========================================================================
// Stage 2: split-K HMMA GEMM (R12-proven). grid NSPLIT, block 256.
static constexpr int S2_ALO = 4608;                  // Ahi @0
static constexpr int S2_BHI = 9216;                  // Bhi [64 k][68]
static constexpr int S2_BLO = S2_BHI + 64 * XSTR;    // 13568
static constexpr int S2_WORDS = S2_BLO + 64 * XSTR;  // 17920
static constexpr int S2_BYTES = S2_WORDS * 4;        // 71680

__global__ __launch_bounds__(256, 2)
void k_gemm_mma(const float* __restrict__ W1) {
    extern __shared__ uint32_t smw[];
    uint32_t* Bhi = smw + S2_BHI;
    uint32_t* Blo = smw + S2_BLO;
    const uint32_t smb = smem_u32(smw);

    const int tid = threadIdx.x;
    const int wid = tid >> 5;
    const int lid = tid & 31;
    const int mbase = (wid >> 2) * 64;
    const int nbase = (wid & 3) * 32;
    const int g  = lid >> 2;
    const int tg = lid & 3;

    const uint32_t aOff = (uint32_t)(mbase + (lid & 15)) * (PSTR * 4) + (lid >> 4) * 16;
    const uint32_t aAhi = smb + aOff;
    const uint32_t aAlo = smb + (uint32_t)S2_ALO * 4 + aOff;
    const uint32_t bOff = (uint32_t)(lid & 15) * (XSTR * 4) + (uint32_t)(nbase + (lid >> 4) * 8) * 2;
    const uint32_t aBhi = smb + (uint32_t)S2_BHI * 4 + bOff;
    const uint32_t aBlo = smb + (uint32_t)S2_BLO * 4 + bOff;

    float acc[4][4][4];
#pragma unroll
    for (int mt = 0; mt < 4; mt++)
#pragma unroll
        for (int nt = 0; nt < 4; nt++)
#pragma unroll
            for (int r = 0; r < 4; r++) acc[mt][nt][r] = 0.f;

    for (int c = blockIdx.x; c < NCHUNK2; c += NSPLIT) {
        const uint32_t kp_base = (uint32_t)c * KPC;
        __syncthreads();   // prev fragment loads done

        // ---- A prefetch: cp.async raw plane copies ----
#pragma unroll
        for (int it = 0; it < 4; it++) {
            int idx = it * 256 + tid;
            int row = idx >> 3;
            int q4  = (idx & 7) * 4;
            CPA16(smb + (uint32_t)(row * PSTR + q4) * 4,
                  &g_Fhi[(size_t)row * FROWP + kp_base + q4]);
        }
#pragma unroll
        for (int it = 0; it < 4; it++) {
            int idx = it * 256 + tid;
            int row = idx >> 3;
            int q4  = (idx & 7) * 4;
            CPA16(smb + (uint32_t)(S2_ALO + row * PSTR + q4) * 4,
                  &g_Flo[(size_t)row * FROWP + kp_base + q4]);
        }
        asm volatile("cp.async.commit_group;");

        // ---- B stage: W1 -> [k][n] bf16 planes (coalesced float2) ----
        {
            const uint32_t flat0 = kp_base * 2u;
            const uint32_t ij_s  = flat0 / KXP;
            const int      rem   = (int)(flat0 - ij_s * KXP);
#pragma unroll
            for (int r = 0; r < 8; r++) {
                int kr  = wid * 8 + r;
                int loc = rem + kr;
                int add = (loc >= KXP);
                int cc  = loc - (add ? KXP : 0);
                uint32_t ijq = ij_s + (uint32_t)add;
                bool rv = (cc < KX) && (ijq < NIJ);
                const float* wrow = W1 + ((size_t)ijq * KX + cc) * PF;
#pragma unroll
                for (int h = 0; h < 2; h++) {
                    int cw = lid + h * 32;
                    float2 w = rv ? *reinterpret_cast<const float2*>(wrow + 2 * cw)
                                  : make_float2(0.f, 0.f);
                    uint32_t hw, lw;
                    cvt2(w.x, w.y, hw, lw);
                    Bhi[kr * XSTR + cw] = hw;
                    Blo[kr * XSTR + cw] = lw;
                }
            }
        }
        asm volatile("cp.async.wait_group 0;");
        __syncthreads();

        // ---- compute: 4 ksteps x 3 combos ----
#pragma unroll
        for (int ks = 0; ks < 4; ks++) {
            uint32_t bh[8], bl[8];
            const uint32_t bk = (uint32_t)ks * 16 * (XSTR * 4);
            ldsm4t(bh + 0, aBhi + bk);
            ldsm4t(bh + 4, aBhi + bk + 32);
            ldsm4t(bl + 0, aBlo + bk);
            ldsm4t(bl + 4, aBlo + bk + 32);
#pragma unroll
            for (int mt = 0; mt < 4; mt++) {
                const uint32_t am = (uint32_t)mt * 16 * (PSTR * 4) + (uint32_t)ks * 32;
                uint32_t ah[4], al[4];
                ldsm4(ah, aAhi + am);
                ldsm4(al, aAlo + am);
#pragma unroll
                for (int nt = 0; nt < 4; nt++) {
                    mma_bf16(acc[mt][nt], ah, &bh[2 * nt]);
                    mma_bf16(acc[mt][nt], ah, &bl[2 * nt]);
                    mma_bf16(acc[mt][nt], al, &bh[2 * nt]);
                }
            }
        }
    }

    float* part = &g_part[(size_t)blockIdx.x * (B_ * PF)];
#pragma unroll
    for (int mt = 0; mt < 4; mt++) {
        int row = mbase + mt * 16 + g;
#pragma unroll
        for (int nt = 0; nt < 4; nt++) {
            int col = nbase + nt * 8 + 2 * tg;
            *reinterpret_cast<float2*>(&part[(size_t)row * PF + col]) =
                make_float2(acc[mt][nt][0], acc[mt][nt][1]);
            *reinterpret_cast<float2*>(&part[(size_t)(row + 8) * PF + col]) =
                make_float2(acc[mt][nt][2], acc[mt][nt][3]);
        }
    }
}

// ===========================================================================
__global__ void k_finish(const float* __restrict__ b1, const float* __restrict__ W2,
                         const float* __restrict__ b2, const float* __restrict__ W3,
                         const float* __restrict__ b3, float* __restrict__ out) {
    __shared__ float h1s[PF];
    __shared__ float red[PF];
    const int b = blockIdx.x;
    const int q = threadIdx.x;

    float s[8];
#pragma unroll
    for (int i = 0; i < 8; i++) s[i] = 0.f;
    const size_t off = (size_t)b * PF + q;
#pragma unroll 2
    for (int c = 0; c < NSPLIT; c += 8) {
#pragma unroll
        for (int i = 0; i < 8; i++)
            s[i] += g_part[(size_t)(c + i) * (B_ * PF) + off];
    }
    float h1 = ((s[0] + s[1]) + (s[2] + s[3])) + ((s[4] + s[5]) + (s[6] + s[7])) + b1[q];
    h1s[q] = fmaxf(h1, 0.f);
    __syncthreads();

    float a0 = b2[q], a1 = 0.f, a2 = 0.f, a3 = 0.f;
#pragma unroll 8
    for (int p = 0; p < PF; p += 4) {
        a0 = fmaf(h1s[p + 0], W2[(p + 0) * PF + q], a0);
        a1 = fmaf(h1s[p + 1], W2[(p + 1) * PF + q], a1);
        a2 = fmaf(h1s[p + 2], W2[(p + 2) * PF + q], a2);
        a3 = fmaf(h1s[p + 3], W2[(p + 3) * PF + q], a3);
    }
    float h2 = fmaxf((a0 + a1) + (a2 + a3), 0.f);

    red[q] = h2 * W3[q];
    __syncthreads();
    for (int sft = 64; sft > 0; sft >>= 1) {
        if (q < sft) red[q] += red[q + sft];
        __syncthreads();
    }
    if (q == 0) {
        float z = red[0] + b3[0];
        out[b] = 6.f / (1.f + expf(-z)) - 3.f;
    }
}

// ---------------------------------------------------------------------------
extern "C" void kernel_launch(void* const* d_in, const int* in_sizes, int n_in,
                              void* d_out, int out_size) {
    const float* audio = (const float*)d_in[0];
    const float* video = (const float*)d_in[1];
    const float* text  = (const float*)d_in[2];
    const float* W1    = (const float*)d_in[3];
    const float* b1    = (const float*)d_in[4];
    const float* W2    = (const float*)d_in[5];
    const float* b2    = (const float*)d_in[6];
    const float* W3    = (const float*)d_in[7];
    const float* b3    = (const float*)d_in[8];
    float* out = (float*)d_out;

    cudaFuncSetAttribute(k_build_F, cudaFuncAttributeMaxDynamicSharedMemorySize, S1_BYTES);
    cudaFuncSetAttribute(k_gemm_mma, cudaFuncAttributeMaxDynamicSharedMemorySize, S2_BYTES);

    k_build_F<<<NSPLIT, 256, S1_BYTES>>>(audio, video, text);
    k_gemm_mma<<<NSPLIT, 256, S2_BYTES>>>(W1);
    k_finish<<<128, 128>>>(b1, W2, b2, W3, b3, out);
}